// round 1
// baseline (speedup 1.0000x reference)
#include <cuda_runtime.h>

#define BDIM 2
#define LDIM 4096
#define HDIM 8
#define DDIM 64
#define MDIM 128
#define CHK  128
#define NCH  (LDIM / CHK)     // 32
#define NBH  (BDIM * HDIM)    // 16

#define TSTRIDE 132           // padded stride for d-major transposed tiles
#define KPTSTRIDE 129         // padded stride for kpT (conflict-free transpose stores)
#define RATIO 0.08838834764831845f   // 1/sqrt(128)
#define STAB  1e-3f

// Scratch (device globals; runtime allocation is forbidden)
__device__ float g_kp[(size_t)NBH * LDIM * MDIM];         // [bh][l][m]   33.5 MB
__device__ float g_S [(size_t)NBH * NCH * MDIM * DDIM];   // [bh][c][m][d] 16.8 MB (raw sums -> exclusive prefix)
__device__ float g_ks[(size_t)NBH * NCH * MDIM];          // [bh][c][m]

// ---------------------------------------------------------------------------
// Pass 1: per-chunk  kp = relu(K P^T * ratio)+eps ;  S_c = kp^T V ; ksum_c
// grid (NCH, NBH), 256 threads
// smem: PsT[64][132] | KsT[64][132] | kps[128][128] | Vs[128][64]
// ---------------------------------------------------------------------------
__global__ __launch_bounds__(256, 1) void pass1_kernel(
    const float* __restrict__ K, const float* __restrict__ V,
    const float* __restrict__ P)
{
    extern __shared__ float sm[];
    float* PsT = sm;                         // 64*132 = 8448
    float* KsT = PsT + 64 * TSTRIDE;         // 8448
    float* kps = KsT + 64 * TSTRIDE;         // 128*128 = 16384
    float* Vs  = kps + CHK * MDIM;           // 128*64 = 8192

    const int chunk = blockIdx.x;
    const int bh    = blockIdx.y;
    const int b     = bh >> 3;
    const int h     = bh & 7;
    const int l0    = chunk * CHK;
    const int tid   = threadIdx.x;

    // Load P transposed: PsT[d][m]
    for (int idx = tid; idx < MDIM * DDIM; idx += 256) {
        int m = idx >> 6, d = idx & 63;
        PsT[d * TSTRIDE + m] = P[idx];
    }
    // Load K chunk transposed KsT[d][c] and V chunk Vs[c][d]
    for (int idx = tid; idx < CHK * DDIM; idx += 256) {
        int c = idx >> 6, d = idx & 63;
        size_t g = ((size_t)((b * LDIM + l0 + c) * HDIM + h)) * DDIM + d;
        KsT[d * TSTRIDE + c] = K[g];
        Vs[c * DDIM + d]     = V[g];
    }
    __syncthreads();

    // kp[c][m] : 4x4 register tiles; lanes vary in m-tile (float4 PsT, broadcast KsT)
    #pragma unroll
    for (int k = 0; k < 4; ++k) {
        const int tile = tid + (k << 8);
        const int m0 = (tile & 31) << 2;
        const int c0 = (tile >> 5) << 2;
        float acc[4][4] = {};
        #pragma unroll 8
        for (int d = 0; d < 64; ++d) {
            float4 c4 = *(const float4*)(KsT + d * TSTRIDE + c0);
            float4 p4 = *(const float4*)(PsT + d * TSTRIDE + m0);
            float cv[4] = {c4.x, c4.y, c4.z, c4.w};
            float pv[4] = {p4.x, p4.y, p4.z, p4.w};
            #pragma unroll
            for (int i = 0; i < 4; ++i)
                #pragma unroll
                for (int j = 0; j < 4; ++j)
                    acc[i][j] = fmaf(cv[i], pv[j], acc[i][j]);
        }
        #pragma unroll
        for (int i = 0; i < 4; ++i) {
            float4 o;
            o.x = fmaxf(acc[i][0] * RATIO, 0.f) + STAB;
            o.y = fmaxf(acc[i][1] * RATIO, 0.f) + STAB;
            o.z = fmaxf(acc[i][2] * RATIO, 0.f) + STAB;
            o.w = fmaxf(acc[i][3] * RATIO, 0.f) + STAB;
            *(float4*)(kps + (c0 + i) * MDIM + m0) = o;
        }
    }
    __syncthreads();

    // S_c[m][d] = sum_c kp[c][m] * V[c][d]  (4m x 4d tiles)
    float* Sout = g_S + ((size_t)(bh * NCH + chunk)) * MDIM * DDIM;
    #pragma unroll
    for (int k = 0; k < 2; ++k) {
        const int tile = tid + (k << 8);
        const int m0 = (tile & 31) << 2;
        const int d0 = (tile >> 5) << 2;
        float acc[4][4] = {};
        #pragma unroll 8
        for (int c = 0; c < CHK; ++c) {
            float4 k4 = *(const float4*)(kps + c * MDIM + m0);
            float4 v4 = *(const float4*)(Vs + c * DDIM + d0);
            float kv[4] = {k4.x, k4.y, k4.z, k4.w};
            float vv[4] = {v4.x, v4.y, v4.z, v4.w};
            #pragma unroll
            for (int i = 0; i < 4; ++i)
                #pragma unroll
                for (int j = 0; j < 4; ++j)
                    acc[i][j] = fmaf(kv[i], vv[j], acc[i][j]);
        }
        #pragma unroll
        for (int i = 0; i < 4; ++i) {
            float4 o = {acc[i][0], acc[i][1], acc[i][2], acc[i][3]};
            *(float4*)(Sout + (m0 + i) * DDIM + d0) = o;
        }
    }
    // ksum_c[m]
    if (tid < MDIM) {
        float s = 0.f;
        #pragma unroll 8
        for (int c = 0; c < CHK; ++c) s += kps[c * MDIM + tid];
        g_ks[(bh * NCH + chunk) * MDIM + tid] = s;
    }
    // store kp to global (coalesced)
    float* kout = g_kp + (size_t)(bh * LDIM + l0) * MDIM;
    for (int idx = tid; idx < CHK * MDIM; idx += 256) kout[idx] = kps[idx];
}

// ---------------------------------------------------------------------------
// Pass 2: in-place exclusive prefix over chunks per (b,h)
// ---------------------------------------------------------------------------
__global__ __launch_bounds__(256, 1) void pass2_kernel()
{
    const int bh = blockIdx.x;
    const int tid = threadIdx.x;
    for (int e = tid; e < MDIM * DDIM; e += 256) {
        float run = 0.f;
        #pragma unroll 4
        for (int c = 0; c < NCH; ++c) {
            size_t off = ((size_t)(bh * NCH + c)) * MDIM * DDIM + e;
            float cur = g_S[off];
            g_S[off] = run;
            run += cur;
        }
    }
    if (tid < MDIM) {
        float run = 0.f;
        #pragma unroll 4
        for (int c = 0; c < NCH; ++c) {
            int off = (bh * NCH + c) * MDIM + tid;
            float cur = g_ks[off];
            g_ks[off] = run;
            run += cur;
        }
    }
}

// ---------------------------------------------------------------------------
// Pass 3: qp features; out = (qp S_pref + tril(qp kp^T) V) / (qp ksum_pref + tril(..) 1)
// grid (NCH, NBH), 256 threads
// smem regions (floats):
//   r0 [0,16896)      : PsT(8448)+QsT(8448)  -> kpT[128][129] (16512)
//   r1 [16896,33280)  : qp [128][128]
//   r2 [33280,49664)  : Ss[128][64]+ksums[128] (phase B)  -> As[128][128] (phase C)
//   r3 [49664,57856)  : Vs [128][64]
// ---------------------------------------------------------------------------
__global__ __launch_bounds__(256, 1) void pass3_kernel(
    const float* __restrict__ Q, const float* __restrict__ V,
    const float* __restrict__ P, float* __restrict__ Out)
{
    extern __shared__ float sm[];
    float* PsT   = sm;
    float* QsT   = sm + 64 * TSTRIDE;
    float* kpT   = sm;                       // stride KPTSTRIDE, reuses r0
    float* qp    = sm + 16896;
    float* Ss    = qp + 16384;
    float* ksums = Ss + MDIM * DDIM;
    float* As    = qp + 16384;               // alias of Ss region
    float* Vs    = qp + 16384 + 16384;

    const int chunk = blockIdx.x;
    const int bh    = blockIdx.y;
    const int b     = bh >> 3;
    const int h     = bh & 7;
    const int l0    = chunk * CHK;
    const int tid   = threadIdx.x;
    const int lane  = tid & 31;
    const int warp  = tid >> 5;

    // Loads
    const float* Sg = g_S + ((size_t)(bh * NCH + chunk)) * MDIM * DDIM;
    for (int idx = tid; idx < MDIM * DDIM; idx += 256) {
        int m = idx >> 6, d = idx & 63;
        PsT[d * TSTRIDE + m] = P[idx];
        Ss[idx] = Sg[idx];
    }
    for (int idx = tid; idx < CHK * DDIM; idx += 256) {
        int c = idx >> 6, d = idx & 63;
        size_t g = ((size_t)((b * LDIM + l0 + c) * HDIM + h)) * DDIM + d;
        QsT[d * TSTRIDE + c] = Q[g];
        Vs[c * DDIM + d]     = V[g];
    }
    if (tid < MDIM) ksums[tid] = g_ks[(bh * NCH + chunk) * MDIM + tid];
    __syncthreads();

    // qp[c][m] = relu(ratio * Q P^T) + eps
    #pragma unroll
    for (int k = 0; k < 4; ++k) {
        const int tile = tid + (k << 8);
        const int m0 = (tile & 31) << 2;
        const int c0 = (tile >> 5) << 2;
        float acc[4][4] = {};
        #pragma unroll 8
        for (int d = 0; d < 64; ++d) {
            float4 c4 = *(const float4*)(QsT + d * TSTRIDE + c0);
            float4 p4 = *(const float4*)(PsT + d * TSTRIDE + m0);
            float cv[4] = {c4.x, c4.y, c4.z, c4.w};
            float pv[4] = {p4.x, p4.y, p4.z, p4.w};
            #pragma unroll
            for (int i = 0; i < 4; ++i)
                #pragma unroll
                for (int j = 0; j < 4; ++j)
                    acc[i][j] = fmaf(cv[i], pv[j], acc[i][j]);
        }
        #pragma unroll
        for (int i = 0; i < 4; ++i) {
            float4 o;
            o.x = fmaxf(acc[i][0] * RATIO, 0.f) + STAB;
            o.y = fmaxf(acc[i][1] * RATIO, 0.f) + STAB;
            o.z = fmaxf(acc[i][2] * RATIO, 0.f) + STAB;
            o.w = fmaxf(acc[i][3] * RATIO, 0.f) + STAB;
            *(float4*)(qp + (c0 + i) * MDIM + m0) = o;
        }
    }
    __syncthreads();   // qp visible; r0 (PsT/QsT) free

    // Load kpT[m][c] (transposed) into r0. Conflict-free stores (stride 129).
    const float* kg = g_kp + (size_t)(bh * LDIM + l0) * MDIM;
    for (int idx = tid; idx < CHK * MDIM; idx += 256) {
        int m = idx & 127, c = idx >> 7;
        kpT[m * KPTSTRIDE + c] = kg[c * MDIM + m];
    }

    // Phase B: inter-chunk  acc += qp @ S_pref ; den += qp . ksum_pref
    const int t0 = warp * 16;
    float accL[16] = {}, accH[16] = {}, den[16] = {};
    #pragma unroll 2
    for (int m = 0; m < MDIM; ++m) {
        float sl = Ss[m * DDIM + lane];
        float sh = Ss[m * DDIM + lane + 32];
        float ks = ksums[m];
        #pragma unroll
        for (int i = 0; i < 16; ++i) {
            float qv = qp[(t0 + i) * MDIM + m];
            accL[i] = fmaf(qv, sl, accL[i]);
            accH[i] = fmaf(qv, sh, accH[i]);
            den[i]  = fmaf(qv, ks, den[i]);
        }
    }
    __syncthreads();   // kpT ready; Ss fully consumed (As may now overwrite r2)

    // Phase C: A = qp kp^T over s <= smax (warp handles rows t0..t0+15)
    const int smax = t0 + 15;
    float a[16][4];
    #pragma unroll
    for (int i = 0; i < 16; ++i)
        #pragma unroll
        for (int j = 0; j < 4; ++j) a[i][j] = 0.f;

    for (int m = 0; m < MDIM; ++m) {
        float qv[16];
        #pragma unroll
        for (int i = 0; i < 16; ++i) qv[i] = qp[(t0 + i) * MDIM + m];
        #pragma unroll
        for (int j = 0; j < 4; ++j) {
            if (j * 32 <= smax) {   // warp-uniform skip of fully-masked s-blocks
                float kv = kpT[m * KPTSTRIDE + j * 32 + lane];
                #pragma unroll
                for (int i = 0; i < 16; ++i) a[i][j] = fmaf(qv[i], kv, a[i][j]);
            }
        }
    }
    // Causal mask + stage into As (warp-private rows)
    #pragma unroll
    for (int i = 0; i < 16; ++i) {
        int t = t0 + i;
        #pragma unroll
        for (int j = 0; j < 4; ++j) {
            int s = j * 32 + lane;
            if (s <= smax) As[t * MDIM + s] = (s <= t) ? a[i][j] : 0.f;
        }
    }
    __syncwarp();

    // Phase C2: acc += tril(A) @ V ; den += rowsum(tril(A))
    for (int s = 0; s <= smax; ++s) {
        float vl = Vs[s * DDIM + lane];
        float vh = Vs[s * DDIM + lane + 32];
        #pragma unroll
        for (int i = 0; i < 16; ++i) {
            float av = As[(t0 + i) * MDIM + s];
            accL[i] = fmaf(av, vl, accL[i]);
            accH[i] = fmaf(av, vh, accH[i]);
            den[i] += av;
        }
    }

    // Epilogue
    #pragma unroll
    for (int i = 0; i < 16; ++i) {
        int l = l0 + t0 + i;
        size_t g = ((size_t)((b * LDIM + l) * HDIM + h)) * DDIM;
        float inv = 1.0f / den[i];
        Out[g + lane]      = accL[i] * inv;
        Out[g + lane + 32] = accH[i] * inv;
    }
}

// ---------------------------------------------------------------------------
extern "C" void kernel_launch(void* const* d_in, const int* in_sizes, int n_in,
                              void* d_out, int out_size)
{
    const float* Q = (const float*)d_in[0];
    const float* K = (const float*)d_in[1];
    const float* V = (const float*)d_in[2];
    const float* P = (const float*)d_in[3];
    float* O = (float*)d_out;

    const int smem1 = (64 * TSTRIDE * 2 + CHK * MDIM + CHK * DDIM) * sizeof(float);  // 165888
    const int smem3 = (16896 + 16384 + 16384 + 8192) * sizeof(float);                // 231424

    cudaFuncSetAttribute(pass1_kernel, cudaFuncAttributeMaxDynamicSharedMemorySize, smem1);
    cudaFuncSetAttribute(pass3_kernel, cudaFuncAttributeMaxDynamicSharedMemorySize, smem3);

    pass1_kernel<<<dim3(NCH, NBH), 256, smem1>>>(K, V, P);
    pass2_kernel<<<NBH, 256>>>();
    pass3_kernel<<<dim3(NCH, NBH), 256, smem3>>>(Q, V, P, O);
}

// round 2
// speedup vs baseline: 1.3357x; 1.3357x over previous
#include <cuda_runtime.h>

#define BDIM 2
#define LDIM 4096
#define HDIM 8
#define DDIM 64
#define MDIM 128
#define CHK  128
#define NCH  (LDIM / CHK)     // 32
#define NBH  (BDIM * HDIM)    // 16

#define TSTRIDE 132           // padded stride for d-major transposed tiles
#define KPTSTRIDE 129         // padded stride for kpT (conflict-free transpose stores)
#define RATIO 0.08838834764831845f   // 1/sqrt(128)
#define STAB  1e-3f

// Scratch (device globals; runtime allocation is forbidden)
__device__ float g_kp[(size_t)NBH * LDIM * MDIM];         // [bh][l][m]
__device__ float g_S [(size_t)NBH * NCH * MDIM * DDIM];   // [bh][c][m][d]
__device__ float g_ks[(size_t)NBH * NCH * MDIM];          // [bh][c][m]

// ---------------------------------------------------------------------------
// Pass 1: per-chunk  kp = relu(K P^T * ratio)+eps ;  S_c = kp^T V ; ksum_c
// grid (NCH, NBH), 512 threads
// ---------------------------------------------------------------------------
__global__ __launch_bounds__(512, 1) void pass1_kernel(
    const float* __restrict__ K, const float* __restrict__ V,
    const float* __restrict__ P)
{
    extern __shared__ float sm[];
    float* PsT = sm;                         // 64*132
    float* KsT = PsT + 64 * TSTRIDE;         // 64*132
    float* kps = KsT + 64 * TSTRIDE;         // 128*128
    float* Vs  = kps + CHK * MDIM;           // 128*64

    const int chunk = blockIdx.x;
    const int bh    = blockIdx.y;
    const int b     = bh >> 3;
    const int h     = bh & 7;
    const int l0    = chunk * CHK;
    const int tid   = threadIdx.x;

    for (int idx = tid; idx < MDIM * DDIM; idx += 512) {
        int m = idx >> 6, d = idx & 63;
        PsT[d * TSTRIDE + m] = P[idx];
    }
    for (int idx = tid; idx < CHK * DDIM; idx += 512) {
        int c = idx >> 6, d = idx & 63;
        size_t g = ((size_t)((b * LDIM + l0 + c) * HDIM + h)) * DDIM + d;
        KsT[d * TSTRIDE + c] = K[g];
        Vs[c * DDIM + d]     = V[g];
    }
    __syncthreads();

    // kp[c][m] : 1024 4x4 tiles, 512 threads -> 2 iterations
    #pragma unroll
    for (int k = 0; k < 2; ++k) {
        const int tile = tid + (k << 9);
        const int m0 = (tile & 31) << 2;
        const int c0 = (tile >> 5) << 2;
        float acc[4][4] = {};
        #pragma unroll 4
        for (int d = 0; d < 64; ++d) {
            float4 c4 = *(const float4*)(KsT + d * TSTRIDE + c0);
            float4 p4 = *(const float4*)(PsT + d * TSTRIDE + m0);
            float cv[4] = {c4.x, c4.y, c4.z, c4.w};
            float pv[4] = {p4.x, p4.y, p4.z, p4.w};
            #pragma unroll
            for (int i = 0; i < 4; ++i)
                #pragma unroll
                for (int j = 0; j < 4; ++j)
                    acc[i][j] = fmaf(cv[i], pv[j], acc[i][j]);
        }
        #pragma unroll
        for (int i = 0; i < 4; ++i) {
            float4 o;
            o.x = fmaxf(acc[i][0] * RATIO, 0.f) + STAB;
            o.y = fmaxf(acc[i][1] * RATIO, 0.f) + STAB;
            o.z = fmaxf(acc[i][2] * RATIO, 0.f) + STAB;
            o.w = fmaxf(acc[i][3] * RATIO, 0.f) + STAB;
            *(float4*)(kps + (c0 + i) * MDIM + m0) = o;
        }
    }
    __syncthreads();

    // S_c[m][d] = sum_c kp[c][m] * V[c][d]  (512 tiles, 1 iteration)
    float* Sout = g_S + ((size_t)(bh * NCH + chunk)) * MDIM * DDIM;
    {
        const int m0 = (tid & 31) << 2;
        const int d0 = (tid >> 5) << 2;
        float acc[4][4] = {};
        #pragma unroll 4
        for (int c = 0; c < CHK; ++c) {
            float4 k4 = *(const float4*)(kps + c * MDIM + m0);
            float4 v4 = *(const float4*)(Vs + c * DDIM + d0);
            float kv[4] = {k4.x, k4.y, k4.z, k4.w};
            float vv[4] = {v4.x, v4.y, v4.z, v4.w};
            #pragma unroll
            for (int i = 0; i < 4; ++i)
                #pragma unroll
                for (int j = 0; j < 4; ++j)
                    acc[i][j] = fmaf(kv[i], vv[j], acc[i][j]);
        }
        #pragma unroll
        for (int i = 0; i < 4; ++i) {
            float4 o = {acc[i][0], acc[i][1], acc[i][2], acc[i][3]};
            *(float4*)(Sout + (m0 + i) * DDIM + d0) = o;
        }
    }
    if (tid < MDIM) {
        float s = 0.f;
        #pragma unroll 8
        for (int c = 0; c < CHK; ++c) s += kps[c * MDIM + tid];
        g_ks[(bh * NCH + chunk) * MDIM + tid] = s;
    }
    float* kout = g_kp + (size_t)(bh * LDIM + l0) * MDIM;
    for (int idx = tid; idx < CHK * MDIM; idx += 512) kout[idx] = kps[idx];
}

// ---------------------------------------------------------------------------
// Pass 2: in-place exclusive prefix over chunks per (b,h). grid (NBH, 32)
// ---------------------------------------------------------------------------
__global__ __launch_bounds__(256, 4) void pass2_kernel()
{
    const int bh  = blockIdx.x;
    const int e   = blockIdx.y * 256 + threadIdx.x;   // 0..8191
    float run = 0.f;
    #pragma unroll 4
    for (int c = 0; c < NCH; ++c) {
        size_t off = ((size_t)(bh * NCH + c)) * MDIM * DDIM + e;
        float cur = g_S[off];
        g_S[off] = run;
        run += cur;
    }
    if (blockIdx.y == 0 && threadIdx.x < MDIM) {
        float r2 = 0.f;
        #pragma unroll 4
        for (int c = 0; c < NCH; ++c) {
            int off = (bh * NCH + c) * MDIM + threadIdx.x;
            float cur = g_ks[off];
            g_ks[off] = r2;
            r2 += cur;
        }
    }
}

// ---------------------------------------------------------------------------
// Pass 3: qp features; out = (qp S_pref + tril(qp kp^T) V) / (qp ksum_pref + ...)
// grid (NCH, NBH), 512 threads (16 warps, 8 rows per warp)
// ---------------------------------------------------------------------------
__global__ __launch_bounds__(512, 1) void pass3_kernel(
    const float* __restrict__ Q, const float* __restrict__ V,
    const float* __restrict__ P, float* __restrict__ Out)
{
    extern __shared__ float sm[];
    float* PsT   = sm;
    float* QsT   = sm + 64 * TSTRIDE;
    float* kpT   = sm;                       // stride KPTSTRIDE, reuses r0
    float* qp    = sm + 16896;
    float* Ss    = qp + 16384;
    float* ksums = Ss + MDIM * DDIM;
    float* As    = qp + 16384;               // alias of Ss region
    float* Vs    = qp + 16384 + 16384;

    const int chunk = blockIdx.x;
    const int bh    = blockIdx.y;
    const int b     = bh >> 3;
    const int h     = bh & 7;
    const int l0    = chunk * CHK;
    const int tid   = threadIdx.x;
    const int lane  = tid & 31;
    const int warp  = tid >> 5;

    const float* Sg = g_S + ((size_t)(bh * NCH + chunk)) * MDIM * DDIM;
    for (int idx = tid; idx < MDIM * DDIM; idx += 512) {
        int m = idx >> 6, d = idx & 63;
        PsT[d * TSTRIDE + m] = P[idx];
        Ss[idx] = Sg[idx];
    }
    for (int idx = tid; idx < CHK * DDIM; idx += 512) {
        int c = idx >> 6, d = idx & 63;
        size_t g = ((size_t)((b * LDIM + l0 + c) * HDIM + h)) * DDIM + d;
        QsT[d * TSTRIDE + c] = Q[g];
        Vs[c * DDIM + d]     = V[g];
    }
    if (tid < MDIM) ksums[tid] = g_ks[(bh * NCH + chunk) * MDIM + tid];
    __syncthreads();

    // qp[c][m] = relu(ratio * Q P^T) + eps   (1024 tiles, 2 iterations)
    #pragma unroll
    for (int k = 0; k < 2; ++k) {
        const int tile = tid + (k << 9);
        const int m0 = (tile & 31) << 2;
        const int c0 = (tile >> 5) << 2;
        float acc[4][4] = {};
        #pragma unroll 4
        for (int d = 0; d < 64; ++d) {
            float4 c4 = *(const float4*)(QsT + d * TSTRIDE + c0);
            float4 p4 = *(const float4*)(PsT + d * TSTRIDE + m0);
            float cv[4] = {c4.x, c4.y, c4.z, c4.w};
            float pv[4] = {p4.x, p4.y, p4.z, p4.w};
            #pragma unroll
            for (int i = 0; i < 4; ++i)
                #pragma unroll
                for (int j = 0; j < 4; ++j)
                    acc[i][j] = fmaf(cv[i], pv[j], acc[i][j]);
        }
        #pragma unroll
        for (int i = 0; i < 4; ++i) {
            float4 o;
            o.x = fmaxf(acc[i][0] * RATIO, 0.f) + STAB;
            o.y = fmaxf(acc[i][1] * RATIO, 0.f) + STAB;
            o.z = fmaxf(acc[i][2] * RATIO, 0.f) + STAB;
            o.w = fmaxf(acc[i][3] * RATIO, 0.f) + STAB;
            *(float4*)(qp + (c0 + i) * MDIM + m0) = o;
        }
    }
    __syncthreads();   // qp visible; r0 (PsT/QsT) free

    // Load kpT[m][c] (transposed) into r0. Conflict-free stores (stride 129).
    const float* kg = g_kp + (size_t)(bh * LDIM + l0) * MDIM;
    for (int idx = tid; idx < CHK * MDIM; idx += 512) {
        int m = idx & 127, c = idx >> 7;
        kpT[m * KPTSTRIDE + c] = kg[c * MDIM + m];
    }

    // Phase B: inter-chunk  acc += qp @ S_pref ; den += qp . ksum_pref
    const int t0 = warp * 8;
    float accL[8] = {}, accH[8] = {}, den[8] = {};
    for (int m = 0; m < MDIM; m += 4) {
        float4 qv4[8];
        #pragma unroll
        for (int i = 0; i < 8; ++i)
            qv4[i] = *(const float4*)(qp + (t0 + i) * MDIM + m);
        #pragma unroll
        for (int mm = 0; mm < 4; ++mm) {
            float sl = Ss[(m + mm) * DDIM + lane];
            float sh = Ss[(m + mm) * DDIM + lane + 32];
            float ks = ksums[m + mm];
            #pragma unroll
            for (int i = 0; i < 8; ++i) {
                float qv = ((const float*)&qv4[i])[mm];
                accL[i] = fmaf(qv, sl, accL[i]);
                accH[i] = fmaf(qv, sh, accH[i]);
                den[i]  = fmaf(qv, ks, den[i]);
            }
        }
    }
    __syncthreads();   // kpT ready; Ss fully consumed (As may now overwrite r2)

    // Phase C: A = qp kp^T over s <= smax (warp w handles rows w*8..w*8+7)
    // Active s-block counts per SMSP {p,p+4,p+8,p+12} = 1+2+3+4 -> balanced.
    const int smax = t0 + 7;
    float a[8][4];
    #pragma unroll
    for (int i = 0; i < 8; ++i)
        #pragma unroll
        for (int j = 0; j < 4; ++j) a[i][j] = 0.f;

    for (int m = 0; m < MDIM; m += 4) {
        float4 qv4[8];
        #pragma unroll
        for (int i = 0; i < 8; ++i)
            qv4[i] = *(const float4*)(qp + (t0 + i) * MDIM + m);
        #pragma unroll
        for (int mm = 0; mm < 4; ++mm) {
            #pragma unroll
            for (int j = 0; j < 4; ++j) {
                if (j * 32 <= smax) {   // warp-uniform block skip
                    float kv = kpT[(m + mm) * KPTSTRIDE + j * 32 + lane];
                    #pragma unroll
                    for (int i = 0; i < 8; ++i) {
                        float qv = ((const float*)&qv4[i])[mm];
                        a[i][j] = fmaf(qv, kv, a[i][j]);
                    }
                }
            }
        }
    }
    // Causal mask + stage into As (warp-private rows)
    #pragma unroll
    for (int i = 0; i < 8; ++i) {
        int t = t0 + i;
        #pragma unroll
        for (int j = 0; j < 4; ++j) {
            int s = j * 32 + lane;
            if (s <= smax) As[t * MDIM + s] = (s <= t) ? a[i][j] : 0.f;
        }
    }
    __syncwarp();

    // Phase C2: acc += tril(A) @ V ; den += rowsum(tril(A))
    for (int s = 0; s <= smax; s += 4) {
        float4 a4[8];
        #pragma unroll
        for (int i = 0; i < 8; ++i)
            a4[i] = *(const float4*)(As + (t0 + i) * MDIM + s);
        #pragma unroll
        for (int ss = 0; ss < 4; ++ss) {
            float vl = Vs[(s + ss) * DDIM + lane];
            float vh = Vs[(s + ss) * DDIM + lane + 32];
            #pragma unroll
            for (int i = 0; i < 8; ++i) {
                float av = ((const float*)&a4[i])[ss];
                accL[i] = fmaf(av, vl, accL[i]);
                accH[i] = fmaf(av, vh, accH[i]);
                den[i] += av;
            }
        }
    }

    // Epilogue
    #pragma unroll
    for (int i = 0; i < 8; ++i) {
        int l = l0 + t0 + i;
        size_t g = ((size_t)((b * LDIM + l) * HDIM + h)) * DDIM;
        float inv = 1.0f / den[i];
        Out[g + lane]      = accL[i] * inv;
        Out[g + lane + 32] = accH[i] * inv;
    }
}

// ---------------------------------------------------------------------------
extern "C" void kernel_launch(void* const* d_in, const int* in_sizes, int n_in,
                              void* d_out, int out_size)
{
    const float* Q = (const float*)d_in[0];
    const float* K = (const float*)d_in[1];
    const float* V = (const float*)d_in[2];
    const float* P = (const float*)d_in[3];
    float* O = (float*)d_out;

    const int smem1 = (64 * TSTRIDE * 2 + CHK * MDIM + CHK * DDIM) * sizeof(float);  // 165888
    const int smem3 = (16896 + 16384 + 16384 + 8192) * sizeof(float);                // 231424

    cudaFuncSetAttribute(pass1_kernel, cudaFuncAttributeMaxDynamicSharedMemorySize, smem1);
    cudaFuncSetAttribute(pass3_kernel, cudaFuncAttributeMaxDynamicSharedMemorySize, smem3);

    pass1_kernel<<<dim3(NCH, NBH), 512, smem1>>>(K, V, P);
    pass2_kernel<<<dim3(NBH, NCH), 256>>>();
    pass3_kernel<<<dim3(NCH, NBH), 512, smem3>>>(Q, V, P, O);
}